// round 16
// baseline (speedup 1.0000x reference)
#include <cuda_runtime.h>
#include <cuda.h>
#include <stdint.h>
#include <math.h>

// HighPassFilter: order-2 IIR biquad, 256 sequences of T=65536 float32.
// R16: TMA everywhere it's legal. Evidence: five structurally different
// kernels plateau at ncu ~22.2us; wavefront accounting shows 160 L1
// wavefronts/tile/warp (~24k cycles/SM) is the invariant closest to the
// kernel time. This round: in-bounds tiles (t>=3, exactly the emitted ones)
// load via one cp.async.bulk.tensor.3d (SW128 == our XOR swizzle) and store
// via one TMA store -- removing the 8 LDGSTS + 8 LDS + 8 STG per tile.
// Warm-up tiles (t<3) keep the validated guarded cp.async path. Compute is
// R15's lookahead-4. Partition: CHUNK=256, WARM=96, NBUF=4 ring + mbarriers.

#define T_LEN   65536
#define CHUNK   256
#define WARM    96
#define JT      32
#define NT      11      // (CHUNK+WARM)/JT
#define NBUF    4
#define BLOCK_WARPS 2
#define BUFBYTES 4096   // 32 rows x 128B

__device__ __forceinline__ void cp_async16(uint32_t dst_smem, const float* src, int src_size)
{
    asm volatile("cp.async.cg.shared.global [%0], [%1], 16, %2;\n"
                 :: "r"(dst_smem), "l"(src), "r"(src_size));
}

__device__ __forceinline__ uint32_t smem_u32(const void* p)
{
    uint32_t a;
    asm("{ .reg .u64 t; cvta.to.shared.u64 t, %1; cvt.u32.u64 %0, t; }"
        : "=r"(a) : "l"(p));
    return a;
}

__global__ __launch_bounds__(BLOCK_WARPS * 32, 1)
void biquad_hp_kernel(const float* __restrict__ x,
                      const __grid_constant__ CUtensorMap tmx,
                      const __grid_constant__ CUtensorMap tmy,
                      float b0, float b1, float b2, float na1, float na2,
                      float pp1, float qq1, float pp2, float qq2,
                      float pp3, float qq3)
{
    __shared__ __align__(16) float tile[BLOCK_WARPS][NBUF][32][32];
    __shared__ __align__(8) unsigned long long mbar[BLOCK_WARPS][NBUF];

    const int w    = threadIdx.x >> 5;
    const int lane = threadIdx.x & 31;
    const int g    = lane >> 3;
    const int m    = lane & 7;

    const int gw   = blockIdx.x * BLOCK_WARPS + w;
    const int seq  = gw >> 3;
    const int wseq = gw & 7;

    const float* xs = x + (long long)seq * T_LEN;
    const int warpbase  = wseq * (32 * CHUNK);
    const int slotbase  = warpbase + g * CHUNK + 4 * m;
    const int chunkbase = seq * 256 + wseq * 32;   // d2 coordinate base

    const uint32_t ringbase = smem_u32(&tile[w][0][0][0]);
    const uint32_t mbase    = smem_u32(&mbar[w][0]);

    if (lane == 0) {
        #pragma unroll
        for (int b = 0; b < NBUF; ++b)
            asm volatile("mbarrier.init.shared.b64 [%0], 1;"
                         :: "r"(mbase + 8u * b) : "memory");
    }
    __syncwarp();

    // cp.async dst swizzle (identical to TMA SW128): row r=4it+g, quad m^(r&7)
    const uint32_t off0 = (uint32_t)g * 128u + (uint32_t)((m ^ g) << 4);
    const uint32_t off1 = off0 ^ 64u;

    float xm1 = 0.f, xm2 = 0.f, ym1 = 0.f, ym2 = 0.f;

    // ---- prologue: cp.async warm-up tiles 0 and 1 (guarded, zero-fill)
    #pragma unroll
    for (int pt = 0; pt < 2; ++pt) {
        const int jt = -WARM + pt * JT;
        const uint32_t dbase = ringbase + (uint32_t)pt * BUFBYTES;
        #pragma unroll
        for (int it = 0; it < 8; ++it) {
            int p = slotbase + it * 1024 + jt;
            uint32_t d = dbase + (uint32_t)(it << 9) + ((it & 1) ? off1 : off0);
            cp_async16(d, xs + (p >= 0 ? p : 0), p >= 0 ? 16 : 0);
        }
        asm volatile("cp.async.commit_group;\n");
    }

    #pragma unroll
    for (int t = 0; t < NT; ++t) {
        const bool emit = (t >= 3);
        float* buf = &tile[w][t & 3][0][0];
        float* row = buf + lane * 32;
        const int lq = lane & 7;

        // ---- recycle buffers: ensure old TMA stores finished reading SMEM.
        //      (ordered for all lanes by the syncwarp below)
        if (t >= 4 && lane == 0)
            asm volatile("cp.async.bulk.wait_group.read 1;\n" ::: "memory");

        // ---- issue load for tile t+2
        if (t == 0) {
            // warm-up tile 2 via guarded cp.async
            const uint32_t dbase = ringbase + 2u * BUFBYTES;
            #pragma unroll
            for (int it = 0; it < 8; ++it) {
                int p = slotbase + it * 1024 + (-WARM + 2 * JT);
                uint32_t d = dbase + (uint32_t)(it << 9) + ((it & 1) ? off1 : off0);
                cp_async16(d, xs + (p >= 0 ? p : 0), p >= 0 ? 16 : 0);
            }
            asm volatile("cp.async.commit_group;\n");
        } else if (t + 2 < NT && lane == 0) {
            const int tt = t + 2;                      // 3..10, always in-bounds
            const uint32_t dst = ringbase + (uint32_t)(tt & 3) * BUFBYTES;
            const uint32_t mb  = mbase + 8u * (tt & 3);
            asm volatile("mbarrier.arrive.expect_tx.shared.b64 _, [%0], %1;"
                         :: "r"(mb), "r"(4096) : "memory");
            asm volatile("cp.async.bulk.tensor.3d.shared::cta.global.tile"
                         ".mbarrier::complete_tx::bytes [%0], [%1, {%2, %3, %4}], [%5];"
                         :: "r"(dst), "l"(&tmx), "r"(0), "r"(tt - 3),
                            "r"(chunkbase), "r"(mb) : "memory");
        }

        // ---- wait for tile t
        if      (t == 0) asm volatile("cp.async.wait_group 2;\n" ::: "memory");
        else if (t == 1) asm volatile("cp.async.wait_group 1;\n" ::: "memory");
        else if (t == 2) asm volatile("cp.async.wait_group 0;\n" ::: "memory");
        else {
            const uint32_t mb = mbase + 8u * (t & 3);
            const uint32_t parity = (uint32_t)(((t - 3) >> 2) & 1);
            asm volatile(
                "{\n\t.reg .pred P;\n\t"
                "WL%=:\n\t"
                "mbarrier.try_wait.parity.acquire.cta.shared::cta.b64 P, [%0], %1, 0x989680;\n\t"
                "@P bra.uni WD%=;\n\t"
                "bra.uni WL%=;\n\t"
                "WD%=:\n\t}"
                :: "r"(mb), "r"(parity) : "memory");
        }
        __syncwarp();

        // ---- advance 32 samples via lookahead-4 (validated in R15)
        #pragma unroll
        for (int jj = 0; jj < JT; jj += 4) {
            const int colq = ((jj >> 2) ^ lq) << 2;
            float4 xv = *reinterpret_cast<float4*>(&row[colq]);

            float t0 = fmaf(b2, xm2, fmaf(b1, xm1, b0 * xv.x));
            float t1 = fmaf(b2, xm1, fmaf(b1, xv.x, b0 * xv.y));
            float t2 = fmaf(b2, xv.x, fmaf(b1, xv.y, b0 * xv.z));
            float t3 = fmaf(b2, xv.y, fmaf(b1, xv.z, b0 * xv.w));

            float T1 = fmaf(na1, t0, t1);
            float T2 = fmaf(na1, T1, fmaf(na2, t0, t2));
            float T3 = fmaf(na1, T2, fmaf(na2, T1, t3));

            float o0 = fmaf(na2, ym2, fmaf(na1, ym1, t0));
            float o1 = fmaf(qq1, ym2, fmaf(pp1, ym1, T1));
            float o2 = fmaf(qq2, ym2, fmaf(pp2, ym1, T2));
            float o3 = fmaf(qq3, ym2, fmaf(pp3, ym1, T3));

            xm2 = xv.z; xm1 = xv.w;
            ym2 = o2;   ym1 = o3;

            if (emit)
                *reinterpret_cast<float4*>(&row[colq]) =
                    make_float4(o0, o1, o2, o3);
        }
        __syncwarp();

        // ---- TMA store of the computed tile (one op; engine de-swizzles)
        if (emit && lane == 0) {
            asm volatile("fence.proxy.async.shared::cta;" ::: "memory");
            const uint32_t src = ringbase + (uint32_t)(t & 3) * BUFBYTES;
            asm volatile("cp.async.bulk.tensor.3d.global.shared::cta.tile.bulk_group"
                         " [%0, {%1, %2, %3}], [%4];"
                         :: "l"(&tmy), "r"(0), "r"(t - 3), "r"(chunkbase),
                            "r"(src) : "memory");
            asm volatile("cp.async.bulk.commit_group;\n" ::: "memory");
        }
    }

    if (lane == 0)
        asm volatile("cp.async.bulk.wait_group 0;\n" ::: "memory");
}

typedef CUresult (*EncodeFn)(
    CUtensorMap*, CUtensorMapDataType, cuuint32_t, void*,
    const cuuint64_t*, const cuuint64_t*, const cuuint32_t*, const cuuint32_t*,
    CUtensorMapInterleave, CUtensorMapSwizzle, CUtensorMapL2promotion,
    CUtensorMapFloatOOBfill);

extern "C" void kernel_launch(void* const* d_in, const int* in_sizes, int n_in,
                              void* d_out, int out_size)
{
    const float* x = (const float*)d_in[0];
    float*       y = (float*)d_out;

    const int total = in_sizes[0];
    const int nseq  = total / T_LEN;          // 256 for the given shapes

    // driver entry point without -lcuda
    void* fp = nullptr;
    cudaDriverEntryPointQueryResult qst;
    cudaGetDriverEntryPointByVersion("cuTensorMapEncodeTiled", &fp, 12000,
                                     cudaEnableDefault, &qst);
    EncodeFn enc = (EncodeFn)fp;

    // 3D view of the stream: [32 samples, 8 tile-rows, nchunks], f32, SW128
    cuuint64_t dims[3]    = {32, 8, (cuuint64_t)(total / CHUNK)};
    cuuint64_t strides[2] = {128, 1024};       // bytes
    cuuint32_t box[3]     = {32, 1, 32};
    cuuint32_t es[3]      = {1, 1, 1};

    CUtensorMap tmx, tmy;
    enc(&tmx, CU_TENSOR_MAP_DATA_TYPE_FLOAT32, 3, (void*)x, dims, strides, box, es,
        CU_TENSOR_MAP_INTERLEAVE_NONE, CU_TENSOR_MAP_SWIZZLE_128B,
        CU_TENSOR_MAP_L2_PROMOTION_L2_128B, CU_TENSOR_MAP_FLOAT_OOB_FILL_NONE);
    enc(&tmy, CU_TENSOR_MAP_DATA_TYPE_FLOAT32, 3, (void*)y, dims, strides, box, es,
        CU_TENSOR_MAP_INTERLEAVE_NONE, CU_TENSOR_MAP_SWIZZLE_128B,
        CU_TENSOR_MAP_L2_PROMOTION_L2_128B, CU_TENSOR_MAP_FLOAT_OOB_FILL_NONE);

    const double w0    = 2.0 * M_PI * (700.0 / 16000.0);
    const double cw    = cos(w0);
    const double sw    = sin(w0);
    const double q     = 0.70710678;
    const double alpha = sw / (2.0 * q);
    const double a0    = 1.0 + alpha;

    const double b0d = ((1.0 + cw) / 2.0) / a0;
    const double b1d = (-(1.0 + cw)) / a0;
    const double a1d = (-2.0 * cw) / a0;
    const double a2d = (1.0 - alpha) / a0;

    const double n1 = -a1d, n2 = -a2d;
    const double p1 = n1 * n1 + n2,       q1 = n1 * n2;
    const double p2 = n1 * p1 + n2 * n1,  q2 = n1 * q1 + n2 * n2;
    const double p3 = n1 * p2 + n2 * p1,  q3 = n1 * q2 + n2 * q1;

    const int warps_total = nseq * 8;
    const int grid        = warps_total / BLOCK_WARPS;   // 1024
    biquad_hp_kernel<<<grid, BLOCK_WARPS * 32>>>(
        x, tmx, tmy,
        (float)b0d, (float)b1d, (float)b0d,
        (float)n1, (float)n2,
        (float)p1, (float)q1, (float)p2, (float)q2, (float)p3, (float)q3);
}